// round 12
// baseline (speedup 1.0000x reference)
#include <cuda_runtime.h>
#include <cuda_fp16.h>
#include <cstdint>

#define BB 2
#define SS 2048
#define DD 512
#define HH 8

// Scratch (allocation-free: __device__ globals)
__device__ half  g_qin[BB * SS * DD];
__device__ half  g_kin[BB * SS * DD];
__device__ half  g_vin[BB * SS * DD];
__device__ half  g_Wqh[DD * DD];
__device__ half  g_Wkh[DD * DD];
__device__ half  g_Wvh[DD * DD];
__device__ half  g_Woh[DD * DD];
__device__ half  g_Qh[BB * SS * DD];
__device__ half  g_Kh[BB * SS * DD];
__device__ half  g_Vh[BB * SS * DD];
__device__ half  g_ctxh[BB * SS * DD];

// ---------------------------------------------------------------------------
// Helpers
// ---------------------------------------------------------------------------
__device__ __forceinline__ void mma_f16(float* d, const uint32_t* a, const uint32_t* b) {
    asm volatile(
        "mma.sync.aligned.m16n8k16.row.col.f32.f16.f16.f32 "
        "{%0,%1,%2,%3}, {%4,%5,%6,%7}, {%8,%9}, {%0,%1,%2,%3};"
        : "+f"(d[0]), "+f"(d[1]), "+f"(d[2]), "+f"(d[3])
        : "r"(a[0]), "r"(a[1]), "r"(a[2]), "r"(a[3]), "r"(b[0]), "r"(b[1]));
}
__device__ __forceinline__ void ldsm_x4(uint32_t& r0, uint32_t& r1, uint32_t& r2,
                                        uint32_t& r3, uint32_t addr) {
    asm volatile("ldmatrix.sync.aligned.m8n8.x4.shared.b16 {%0,%1,%2,%3}, [%4];"
                 : "=r"(r0), "=r"(r1), "=r"(r2), "=r"(r3) : "r"(addr));
}
__device__ __forceinline__ void ldsm_x4_t(uint32_t& r0, uint32_t& r1, uint32_t& r2,
                                          uint32_t& r3, uint32_t addr) {
    asm volatile("ldmatrix.sync.aligned.m8n8.x4.trans.shared.b16 {%0,%1,%2,%3}, [%4];"
                 : "=r"(r0), "=r"(r1), "=r"(r2), "=r"(r3) : "r"(addr));
}
__device__ __forceinline__ uint32_t smem_u32(const void* p) {
    uint32_t a;
    asm("{ .reg .u64 t; cvta.to.shared.u64 t, %1; cvt.u32.u64 %0, t; }"
        : "=r"(a) : "l"(p));
    return a;
}
__device__ __forceinline__ uint32_t pack_h2(float a, float b) {
    __half2 h = __floats2half2_rn(a, b);
    return *reinterpret_cast<uint32_t*>(&h);
}
__device__ __forceinline__ void cp16(uint32_t dst, const void* src) {
    asm volatile("cp.async.cg.shared.global [%0], [%1], 16;" :: "r"(dst), "l"(src));
}
__device__ __forceinline__ void cp_commit() {
    asm volatile("cp.async.commit_group;" ::: "memory");
}
template <int N>
__device__ __forceinline__ void cp_wait() {
    asm volatile("cp.async.wait_group %0;" :: "n"(N) : "memory");
}

// ===========================================================================
// Convert kernel: fp32 -> fp16 for q,k,v inputs and Wq,Wk,Wv,Wo
// ===========================================================================
__global__ __launch_bounds__(256)
void convert_kernel(const float4* q, const float4* k, const float4* v,
                    const float4* wq, const float4* wk, const float4* wv,
                    const float4* wo,
                    uint2* qh, uint2* kh, uint2* vh,
                    uint2* wqh, uint2* wkh, uint2* wvh, uint2* woh) {
    const int NI = BB * SS * DD / 4;   // 524288
    const int NW = DD * DD / 4;        // 65536
    int i = blockIdx.x * 256 + threadIdx.x;
    const float4* src; uint2* dst; int off;
    if (i < NI)                   { src = q;  dst = qh;  off = i; }
    else if (i < 2 * NI)          { src = k;  dst = kh;  off = i - NI; }
    else if (i < 3 * NI)          { src = v;  dst = vh;  off = i - 2 * NI; }
    else if (i < 3 * NI + NW)     { src = wq; dst = wqh; off = i - 3 * NI; }
    else if (i < 3 * NI + 2 * NW) { src = wk; dst = wkh; off = i - 3 * NI - NW; }
    else if (i < 3 * NI + 3 * NW) { src = wv; dst = wvh; off = i - 3 * NI - 2 * NW; }
    else                          { src = wo; dst = woh; off = i - 3 * NI - 3 * NW; }
    float4 x = src[off];
    dst[off] = make_uint2(pack_h2(x.x, x.y), pack_h2(x.z, x.w));
}

// ===========================================================================
// gemm3_h: fused Q/K/V projections. 128x128 tile, BK=32, 4-stage cp.async.
// Stage (halfs): A[128][40] (5120) + W[32][136] (4352) = 9472.
// z==0 (Q) scaled by 1/8 in epilogue. (Round-9 body, near tensor floor.)
// ===========================================================================
__global__ __launch_bounds__(256, 2)
void gemm3_h(const half* A0, const half* A1, const half* A2,
             const half* W0, const half* W1, const half* W2,
             const float* b0, const float* b1, const float* b2,
             half* C0, half* C1, half* C2, int M, int N, int K) {
    extern __shared__ half smh[];
    const uint32_t sm_base = smem_u32(smh);

    const int z = blockIdx.z;
    const half* A = (z == 0) ? A0 : (z == 1) ? A1 : A2;
    const half* W = (z == 0) ? W0 : (z == 1) ? W1 : W2;
    const float* bias = (z == 0) ? b0 : (z == 1) ? b1 : b2;
    half* C = (z == 0) ? C0 : (z == 1) ? C1 : C2;
    const float scale = (z == 0) ? 0.125f : 1.0f;

    const int tid = threadIdx.x;
    const int warp = tid >> 5;
    const int lane = tid & 31;
    const int g = lane >> 2;
    const int tg = lane & 3;
    const int wm = warp & 3;
    const int wn = warp >> 2;
    const int m0 = blockIdx.x * 128;
    const int n0 = blockIdx.y * 128;

    auto issue_stage = [&](int kc, int s) {
        const uint32_t sa = sm_base + (uint32_t)(s * 9472) * 2;
        const uint32_t sw = sa + 5120 * 2;
#pragma unroll
        for (int t = 0; t < 2; t++) {
            int idx = tid + t * 256;
            int row = idx >> 2, c4 = idx & 3;
            cp16(sa + (uint32_t)(row * 40 + c4 * 8) * 2,
                 A + (size_t)(m0 + row) * K + kc * 32 + c4 * 8);
        }
#pragma unroll
        for (int t = 0; t < 2; t++) {
            int idx = tid + t * 256;
            int row = idx >> 4, c16 = idx & 15;
            cp16(sw + (uint32_t)(row * 136 + c16 * 8) * 2,
                 W + (size_t)(kc * 32 + row) * N + n0 + c16 * 8);
        }
        cp_commit();
    };

    float acc[2][8][4];
#pragma unroll
    for (int mi = 0; mi < 2; mi++)
#pragma unroll
        for (int nj = 0; nj < 8; nj++)
#pragma unroll
            for (int c = 0; c < 4; c++) acc[mi][nj][c] = 0.0f;

    issue_stage(0, 0);
    issue_stage(1, 1);

    const int nk = K / 32;
    for (int kc = 0; kc < nk; kc++) {
        const int s = kc & 3;
        if (kc + 2 < nk) { issue_stage(kc + 2, (kc + 2) & 3); cp_wait<2>(); }
        else if (kc + 1 < nk) { cp_wait<1>(); }
        else { cp_wait<0>(); }
        __syncthreads();

        const uint32_t a_base = sm_base + (uint32_t)(s * 9472) * 2;
        const uint32_t w_base = a_base + 5120 * 2;
#pragma unroll
        for (int ks = 0; ks < 2; ks++) {
            const int kb = ks * 16;
            uint32_t af[2][4];
#pragma unroll
            for (int mi = 0; mi < 2; mi++) {
                const int row = wm * 32 + mi * 16 + (lane & 15);
                const int col = kb + 8 * (lane >> 4);
                ldsm_x4(af[mi][0], af[mi][1], af[mi][2], af[mi][3],
                        a_base + (uint32_t)(row * 40 + col) * 2);
            }
#pragma unroll
            for (int nj2 = 0; nj2 < 4; nj2++) {
                const int row = kb + (lane & 7) + (((lane >> 3) & 1) * 8);
                const int col = wn * 64 + nj2 * 16 + (((lane >> 4) & 1) * 8);
                uint32_t b0r, b1r, b2r, b3r;
                ldsm_x4_t(b0r, b1r, b2r, b3r, w_base + (uint32_t)(row * 136 + col) * 2);
                uint32_t bb0[2] = {b0r, b1r}, bb1[2] = {b2r, b3r};
                mma_f16(acc[0][2 * nj2], af[0], bb0);
                mma_f16(acc[0][2 * nj2 + 1], af[0], bb1);
                mma_f16(acc[1][2 * nj2], af[1], bb0);
                mma_f16(acc[1][2 * nj2 + 1], af[1], bb1);
            }
        }
    }

#pragma unroll
    for (int mi = 0; mi < 2; mi++) {
        const int rb = m0 + wm * 32 + mi * 16;
#pragma unroll
        for (int nj = 0; nj < 8; nj++) {
            const int colb = n0 + wn * 64 + nj * 8 + 2 * tg;
            const float2 bv = *reinterpret_cast<const float2*>(bias + colb);
            *reinterpret_cast<uint32_t*>(C + (size_t)(rb + g) * N + colb) =
                pack_h2((acc[mi][nj][0] + bv.x) * scale, (acc[mi][nj][1] + bv.y) * scale);
            *reinterpret_cast<uint32_t*>(C + (size_t)(rb + g + 8) * N + colb) =
                pack_h2((acc[mi][nj][2] + bv.x) * scale, (acc[mi][nj][3] + bv.y) * scale);
        }
    }
}

// ===========================================================================
// gemm_out_h: 64x128 tile (256 CTAs = 1 full wave), BK=32, 4-stage cp.async.
// 8 warps as (2 m x 4 n), warp tile 32x32. Stage: A[64][40]=2560 + W=4352.
// ===========================================================================
__global__ __launch_bounds__(256, 2)
void gemm_out_h(const half* __restrict__ A, const half* __restrict__ W,
                const float* __restrict__ bias, float* __restrict__ C,
                int M, int N, int K) {
    extern __shared__ half smh[];
    const uint32_t sm_base = smem_u32(smh);

    const int tid = threadIdx.x;
    const int warp = tid >> 5;
    const int lane = tid & 31;
    const int g = lane >> 2;
    const int tg = lane & 3;
    const int wm = warp & 1;         // 2 m-tiles of 32 rows
    const int wn = warp >> 1;        // 4 n-groups of 32 cols
    const int m0 = blockIdx.x * 64;
    const int n0 = blockIdx.y * 128;

    auto issue_stage = [&](int kc, int s) {
        const uint32_t sa = sm_base + (uint32_t)(s * 6912) * 2;
        const uint32_t sw = sa + 2560 * 2;
        {
            int row = tid >> 2, c4 = tid & 3;   // 256 threads cover 64x32
            cp16(sa + (uint32_t)(row * 40 + c4 * 8) * 2,
                 A + (size_t)(m0 + row) * K + kc * 32 + c4 * 8);
        }
#pragma unroll
        for (int t = 0; t < 2; t++) {
            int idx = tid + t * 256;
            int row = idx >> 4, c16 = idx & 15;
            cp16(sw + (uint32_t)(row * 136 + c16 * 8) * 2,
                 W + (size_t)(kc * 32 + row) * N + n0 + c16 * 8);
        }
        cp_commit();
    };

    float acc[2][4][4];
#pragma unroll
    for (int mi = 0; mi < 2; mi++)
#pragma unroll
        for (int nj = 0; nj < 4; nj++)
#pragma unroll
            for (int c = 0; c < 4; c++) acc[mi][nj][c] = 0.0f;

    issue_stage(0, 0);
    issue_stage(1, 1);

    const int nk = K / 32;
    for (int kc = 0; kc < nk; kc++) {
        const int s = kc & 3;
        if (kc + 2 < nk) { issue_stage(kc + 2, (kc + 2) & 3); cp_wait<2>(); }
        else if (kc + 1 < nk) { cp_wait<1>(); }
        else { cp_wait<0>(); }
        __syncthreads();

        const uint32_t a_base = sm_base + (uint32_t)(s * 6912) * 2;
        const uint32_t w_base = a_base + 2560 * 2;
#pragma unroll
        for (int ks = 0; ks < 2; ks++) {
            const int kb = ks * 16;
            uint32_t af[2][4];
#pragma unroll
            for (int mi = 0; mi < 2; mi++) {
                const int row = wm * 32 + mi * 16 + (lane & 15);
                const int col = kb + 8 * (lane >> 4);
                ldsm_x4(af[mi][0], af[mi][1], af[mi][2], af[mi][3],
                        a_base + (uint32_t)(row * 40 + col) * 2);
            }
#pragma unroll
            for (int nj2 = 0; nj2 < 2; nj2++) {
                const int row = kb + (lane & 7) + (((lane >> 3) & 1) * 8);
                const int col = wn * 32 + nj2 * 16 + (((lane >> 4) & 1) * 8);
                uint32_t b0r, b1r, b2r, b3r;
                ldsm_x4_t(b0r, b1r, b2r, b3r, w_base + (uint32_t)(row * 136 + col) * 2);
                uint32_t bb0[2] = {b0r, b1r}, bb1[2] = {b2r, b3r};
                mma_f16(acc[0][2 * nj2], af[0], bb0);
                mma_f16(acc[0][2 * nj2 + 1], af[0], bb1);
                mma_f16(acc[1][2 * nj2], af[1], bb0);
                mma_f16(acc[1][2 * nj2 + 1], af[1], bb1);
            }
        }
    }

#pragma unroll
    for (int mi = 0; mi < 2; mi++) {
        const int rb = m0 + wm * 32 + mi * 16;
#pragma unroll
        for (int nj = 0; nj < 4; nj++) {
            const int colb = n0 + wn * 32 + nj * 8 + 2 * tg;
            const float2 bv = *reinterpret_cast<const float2*>(bias + colb);
            *reinterpret_cast<float2*>(C + (size_t)(rb + g) * N + colb) =
                make_float2(acc[mi][nj][0] + bv.x, acc[mi][nj][1] + bv.y);
            *reinterpret_cast<float2*>(C + (size_t)(rb + g + 8) * N + colb) =
                make_float2(acc[mi][nj][2] + bv.x, acc[mi][nj][3] + bv.y);
        }
    }
}

// ===========================================================================
// Fused flash attention — fp16 mma, register-resident P, 128-column 2-stage
// cp.async ring with issue-after-barrier (16 barriers, full-tile overlap).
// smem (halfs): Q[128][72] + 2 stages x (K[128][72] + V[128][72]) = 92160 B.
// ===========================================================================
__global__ __launch_bounds__(256, 2)
void attn_kernel(const half* __restrict__ Qg, const half* __restrict__ Kg,
                 const half* __restrict__ Vg, const float* __restrict__ structure,
                 half* __restrict__ ctx) {
    extern __shared__ half smh[];
    const uint32_t qs_base = smem_u32(smh);

    const int tid = threadIdx.x;
    const int warp = tid >> 5;
    const int lane = tid & 31;
    const int g = lane >> 2;
    const int tg = lane & 3;
    const int q0 = blockIdx.x * 128;
    const int h = blockIdx.y;
    const int b = blockIdx.z;
    const int rq = warp * 16;
    const size_t baseQ = ((size_t)b * SS + q0) * DD + h * 64;

    // Stage s (s in {0,1}): K at qs+9216+s*18432 halfs, V at +9216 halfs more.
    auto issue_kv = [&](int t128, int s) {
        const size_t baseK = ((size_t)b * SS + t128 * 128) * DD + h * 64;
        const uint32_t kb = qs_base + (uint32_t)(9216 + s * 18432) * 2;
        const uint32_t vb = kb + 9216 * 2;
#pragma unroll
        for (int t = 0; t < 4; t++) {
            int idx = tid + t * 256;
            int row = idx >> 3, c8 = idx & 7;
            cp16(kb + (uint32_t)(row * 72 + c8 * 8) * 2,
                 Kg + baseK + (size_t)row * DD + c8 * 8);
        }
#pragma unroll
        for (int t = 0; t < 4; t++) {
            int idx = tid + t * 256;
            int row = idx >> 3, c8 = idx & 7;
            cp16(vb + (uint32_t)(row * 72 + c8 * 8) * 2,
                 Vg + baseK + (size_t)row * DD + c8 * 8);
        }
        cp_commit();
    };

    // Prime: tile 0 into stage 0, plus Q tile.
    issue_kv(0, 0);
#pragma unroll
    for (int t = 0; t < 4; t++) {
        int idx = tid + t * 256;
        int row = idx >> 3, c8 = idx & 7;
        cp16(qs_base + (uint32_t)(row * 72 + c8 * 8) * 2,
             Qg + baseQ + (size_t)row * DD + c8 * 8);
    }
    cp_commit();
    cp_wait<0>();
    __syncthreads();

    // Preload Q fragments (persist in registers)
    uint32_t qf[4][4];
#pragma unroll
    for (int ks = 0; ks < 4; ks++) {
        const int row = rq + (lane & 15);
        const int col = ks * 16 + 8 * (lane >> 4);
        ldsm_x4(qf[ks][0], qf[ks][1], qf[ks][2], qf[ks][3],
                qs_base + (uint32_t)(row * 72 + col) * 2);
    }

    float m_[2] = {-1e30f, -1e30f};
    float l_[2] = {0.0f, 0.0f};
    float oacc[8][4];
#pragma unroll
    for (int nj = 0; nj < 8; nj++)
#pragma unroll
        for (int c = 0; c < 4; c++) oacc[nj][c] = 0.0f;

    const int NT = SS / 128;   // 16
    for (int t128 = 0; t128 < NT; t128++) {
        const int s = t128 & 1;
        cp_wait<0>();          // tile t128's data landed
        __syncthreads();       // ...and visible to all warps; prior stage reads done
        if (t128 + 1 < NT) issue_kv(t128 + 1, s ^ 1);   // overlaps full compute below

        const uint32_t stage = qs_base + (uint32_t)(9216 + s * 18432) * 2;

#pragma unroll
        for (int half64 = 0; half64 < 2; half64++) {
            const int k0g = t128 * 128 + half64 * 64;
            const uint32_t ks_base = stage + (uint32_t)(half64 * 64 * 72) * 2;
            const uint32_t vs_base = stage + (uint32_t)(9216 + half64 * 64 * 72) * 2;

            // Structure bias -> score accumulators
            float sacc[8][4];
#pragma unroll
            for (int nj = 0; nj < 8; nj++) {
                const int colb = k0g + nj * 8 + 2 * tg;
                const float2 s0 = *reinterpret_cast<const float2*>(
                    structure + ((size_t)b * SS + q0 + rq + g) * SS + colb);
                const float2 s1 = *reinterpret_cast<const float2*>(
                    structure + ((size_t)b * SS + q0 + rq + g + 8) * SS + colb);
                sacc[nj][0] = s0.x;
                sacc[nj][1] = s0.y;
                sacc[nj][2] = s1.x;
                sacc[nj][3] = s1.y;
            }

            // --- QK^T ---
#pragma unroll
            for (int ks = 0; ks < 4; ks++) {
                const int kb = ks * 16;
#pragma unroll
                for (int nj2 = 0; nj2 < 4; nj2++) {
                    const int row = nj2 * 16 + (lane & 7) + (((lane >> 4) & 1) * 8);
                    const int col = kb + (((lane >> 3) & 1) * 8);
                    uint32_t b0r, b1r, b2r, b3r;
                    ldsm_x4(b0r, b1r, b2r, b3r, ks_base + (uint32_t)(row * 72 + col) * 2);
                    uint32_t bb0[2] = {b0r, b1r}, bb1[2] = {b2r, b3r};
                    mma_f16(sacc[2 * nj2], qf[ks], bb0);
                    mma_f16(sacc[2 * nj2 + 1], qf[ks], bb1);
                }
            }

            // --- Online softmax (max quad-reduced; l per-lane, deferred) ---
#pragma unroll
            for (int h2 = 0; h2 < 2; h2++) {
                float mx = -1e30f;
#pragma unroll
                for (int nj = 0; nj < 8; nj++)
                    mx = fmaxf(mx, fmaxf(sacc[nj][2 * h2], sacc[nj][2 * h2 + 1]));
                mx = fmaxf(mx, __shfl_xor_sync(0xffffffffu, mx, 1));
                mx = fmaxf(mx, __shfl_xor_sync(0xffffffffu, mx, 2));

                const float mn = fmaxf(m_[h2], mx);
                const float al = __expf(m_[h2] - mn);
                float rs = 0.0f;
#pragma unroll
                for (int nj = 0; nj < 8; nj++) {
                    float p0 = __expf(sacc[nj][2 * h2] - mn);
                    float p1 = __expf(sacc[nj][2 * h2 + 1] - mn);
                    sacc[nj][2 * h2] = p0;
                    sacc[nj][2 * h2 + 1] = p1;
                    rs += p0 + p1;
                }
                l_[h2] = l_[h2] * al + rs;
                m_[h2] = mn;
#pragma unroll
                for (int nj = 0; nj < 8; nj++) {
                    oacc[nj][2 * h2] *= al;
                    oacc[nj][2 * h2 + 1] *= al;
                }
            }

            // --- PV with register-resident P ---
#pragma unroll
            for (int ks = 0; ks < 4; ks++) {
                uint32_t pf[4];
                pf[0] = pack_h2(sacc[2 * ks][0],     sacc[2 * ks][1]);
                pf[1] = pack_h2(sacc[2 * ks][2],     sacc[2 * ks][3]);
                pf[2] = pack_h2(sacc[2 * ks + 1][0], sacc[2 * ks + 1][1]);
                pf[3] = pack_h2(sacc[2 * ks + 1][2], sacc[2 * ks + 1][3]);
                const int cb = ks * 16;
#pragma unroll
                for (int db2 = 0; db2 < 4; db2++) {
                    const int row = cb + (lane & 7) + (((lane >> 3) & 1) * 8);
                    const int col = db2 * 16 + (((lane >> 4) & 1) * 8);
                    uint32_t b0r, b1r, b2r, b3r;
                    ldsm_x4_t(b0r, b1r, b2r, b3r, vs_base + (uint32_t)(row * 72 + col) * 2);
                    uint32_t bb0[2] = {b0r, b1r}, bb1[2] = {b2r, b3r};
                    mma_f16(oacc[2 * db2], pf, bb0);
                    mma_f16(oacc[2 * db2 + 1], pf, bb1);
                }
            }
        }
    }

    // Final l reduction across the quad, normalize, write half ctx
#pragma unroll
    for (int h2 = 0; h2 < 2; h2++) {
        l_[h2] += __shfl_xor_sync(0xffffffffu, l_[h2], 1);
        l_[h2] += __shfl_xor_sync(0xffffffffu, l_[h2], 2);
    }
    const float inv0 = 1.0f / l_[0];
    const float inv1 = 1.0f / l_[1];
#pragma unroll
    for (int nj = 0; nj < 8; nj++) {
        const int colb = nj * 8 + 2 * tg;
        *reinterpret_cast<uint32_t*>(ctx + baseQ + (size_t)(rq + g) * DD + colb) =
            pack_h2(oacc[nj][0] * inv0, oacc[nj][1] * inv0);
        *reinterpret_cast<uint32_t*>(ctx + baseQ + (size_t)(rq + g + 8) * DD + colb) =
            pack_h2(oacc[nj][2] * inv1, oacc[nj][3] * inv1);
    }
}

// ===========================================================================
// kernel_launch
// ===========================================================================
extern "C" void kernel_launch(void* const* d_in, const int* in_sizes, int n_in,
                              void* d_out, int out_size) {
    const float* q   = (const float*)d_in[0];
    const float* k   = (const float*)d_in[1];
    const float* v   = (const float*)d_in[2];
    const float* str = (const float*)d_in[3];
    const float* Wq  = (const float*)d_in[4];
    const float* bq  = (const float*)d_in[5];
    const float* Wk  = (const float*)d_in[6];
    const float* bk  = (const float*)d_in[7];
    const float* Wv  = (const float*)d_in[8];
    const float* bv  = (const float*)d_in[9];
    const float* Wo  = (const float*)d_in[10];
    const float* bo  = (const float*)d_in[11];
    float* out = (float*)d_out;

    half *qin, *kin, *vin, *Wqh, *Wkh, *Wvh, *Woh, *Qh, *Kh, *Vh, *Ctxh;
    cudaGetSymbolAddress((void**)&qin, g_qin);
    cudaGetSymbolAddress((void**)&kin, g_kin);
    cudaGetSymbolAddress((void**)&vin, g_vin);
    cudaGetSymbolAddress((void**)&Wqh, g_Wqh);
    cudaGetSymbolAddress((void**)&Wkh, g_Wkh);
    cudaGetSymbolAddress((void**)&Wvh, g_Wvh);
    cudaGetSymbolAddress((void**)&Woh, g_Woh);
    cudaGetSymbolAddress((void**)&Qh, g_Qh);
    cudaGetSymbolAddress((void**)&Kh, g_Kh);
    cudaGetSymbolAddress((void**)&Vh, g_Vh);
    cudaGetSymbolAddress((void**)&Ctxh, g_ctxh);

    const int M = BB * SS;   // 4096
    const int N = DD;        // 512
    const int K = DD;        // 512

    // 1) convert inputs + all weights to fp16
    const int NI = BB * SS * DD / 4, NW = DD * DD / 4;
    convert_kernel<<<(3 * NI + 4 * NW) / 256, 256>>>(
        (const float4*)q, (const float4*)k, (const float4*)v,
        (const float4*)Wq, (const float4*)Wk, (const float4*)Wv, (const float4*)Wo,
        (uint2*)qin, (uint2*)kin, (uint2*)vin,
        (uint2*)Wqh, (uint2*)Wkh, (uint2*)Wvh, (uint2*)Woh);

    // 2) fused Q/K/V projections
    const int gsm3 = 4 * 9472 * (int)sizeof(half);   // 75776 B
    cudaFuncSetAttribute(gemm3_h, cudaFuncAttributeMaxDynamicSharedMemorySize, gsm3);
    dim3 g3(M / 128, N / 128, 3);
    gemm3_h<<<g3, 256, gsm3>>>(qin, kin, vin, Wqh, Wkh, Wvh,
                               bq, bk, bv, Qh, Kh, Vh, M, N, K);

    // 3) attention (half ctx out)
    const int att_smem = (9216 + 2 * 18432) * (int)sizeof(half);   // 92160 B
    cudaFuncSetAttribute(attn_kernel, cudaFuncAttributeMaxDynamicSharedMemorySize,
                         att_smem);
    dim3 att_grid(SS / 128, HH, BB);
    attn_kernel<<<att_grid, 256, att_smem>>>(Qh, Kh, Vh, str, Ctxh);

    // 4) output projection: 64x128 tiles -> 256 CTAs (one full wave)
    const int gsmo = 4 * 6912 * (int)sizeof(half);   // 55296 B
    cudaFuncSetAttribute(gemm_out_h, cudaFuncAttributeMaxDynamicSharedMemorySize, gsmo);
    dim3 gemm_grid(M / 64, N / 128);
    gemm_out_h<<<gemm_grid, 256, gsmo>>>(Ctxh, Woh, bo, out, M, N, K);
}

// round 13
// speedup vs baseline: 1.0309x; 1.0309x over previous
#include <cuda_runtime.h>
#include <cuda_fp16.h>
#include <cstdint>

#define BB 2
#define SS 2048
#define DD 512
#define HH 8

// Scratch (allocation-free: __device__ globals)
__device__ half  g_qin[BB * SS * DD];
__device__ half  g_kin[BB * SS * DD];
__device__ half  g_vin[BB * SS * DD];
__device__ half  g_Wqh[DD * DD];
__device__ half  g_Wkh[DD * DD];
__device__ half  g_Wvh[DD * DD];
__device__ half  g_Woh[DD * DD];
__device__ half  g_Qh[BB * SS * DD];
__device__ half  g_Kh[BB * SS * DD];
__device__ half  g_Vh[BB * SS * DD];
__device__ half  g_ctxh[BB * SS * DD];

// ---------------------------------------------------------------------------
// Helpers
// ---------------------------------------------------------------------------
__device__ __forceinline__ void mma_f16(float* d, const uint32_t* a, const uint32_t* b) {
    asm volatile(
        "mma.sync.aligned.m16n8k16.row.col.f32.f16.f16.f32 "
        "{%0,%1,%2,%3}, {%4,%5,%6,%7}, {%8,%9}, {%0,%1,%2,%3};"
        : "+f"(d[0]), "+f"(d[1]), "+f"(d[2]), "+f"(d[3])
        : "r"(a[0]), "r"(a[1]), "r"(a[2]), "r"(a[3]), "r"(b[0]), "r"(b[1]));
}
__device__ __forceinline__ void ldsm_x4(uint32_t& r0, uint32_t& r1, uint32_t& r2,
                                        uint32_t& r3, uint32_t addr) {
    asm volatile("ldmatrix.sync.aligned.m8n8.x4.shared.b16 {%0,%1,%2,%3}, [%4];"
                 : "=r"(r0), "=r"(r1), "=r"(r2), "=r"(r3) : "r"(addr));
}
__device__ __forceinline__ void ldsm_x4_t(uint32_t& r0, uint32_t& r1, uint32_t& r2,
                                          uint32_t& r3, uint32_t addr) {
    asm volatile("ldmatrix.sync.aligned.m8n8.x4.trans.shared.b16 {%0,%1,%2,%3}, [%4];"
                 : "=r"(r0), "=r"(r1), "=r"(r2), "=r"(r3) : "r"(addr));
}
__device__ __forceinline__ uint32_t smem_u32(const void* p) {
    uint32_t a;
    asm("{ .reg .u64 t; cvta.to.shared.u64 t, %1; cvt.u32.u64 %0, t; }"
        : "=r"(a) : "l"(p));
    return a;
}
__device__ __forceinline__ uint32_t pack_h2(float a, float b) {
    __half2 h = __floats2half2_rn(a, b);
    return *reinterpret_cast<uint32_t*>(&h);
}
__device__ __forceinline__ void cp16(uint32_t dst, const void* src) {
    asm volatile("cp.async.cg.shared.global [%0], [%1], 16;" :: "r"(dst), "l"(src));
}
__device__ __forceinline__ void cp_commit() {
    asm volatile("cp.async.commit_group;" ::: "memory");
}
template <int N>
__device__ __forceinline__ void cp_wait() {
    asm volatile("cp.async.wait_group %0;" :: "n"(N) : "memory");
}

// ===========================================================================
// Convert kernel: fp32 -> fp16 for q,k,v inputs and Wq,Wk,Wv,Wo
// ===========================================================================
__global__ __launch_bounds__(256)
void convert_kernel(const float4* q, const float4* k, const float4* v,
                    const float4* wq, const float4* wk, const float4* wv,
                    const float4* wo,
                    uint2* qh, uint2* kh, uint2* vh,
                    uint2* wqh, uint2* wkh, uint2* wvh, uint2* woh) {
    const int NI = BB * SS * DD / 4;   // 524288
    const int NW = DD * DD / 4;        // 65536
    int i = blockIdx.x * 256 + threadIdx.x;
    const float4* src; uint2* dst; int off;
    if (i < NI)                   { src = q;  dst = qh;  off = i; }
    else if (i < 2 * NI)          { src = k;  dst = kh;  off = i - NI; }
    else if (i < 3 * NI)          { src = v;  dst = vh;  off = i - 2 * NI; }
    else if (i < 3 * NI + NW)     { src = wq; dst = wqh; off = i - 3 * NI; }
    else if (i < 3 * NI + 2 * NW) { src = wk; dst = wkh; off = i - 3 * NI - NW; }
    else if (i < 3 * NI + 3 * NW) { src = wv; dst = wvh; off = i - 3 * NI - 2 * NW; }
    else                          { src = wo; dst = woh; off = i - 3 * NI - 3 * NW; }
    float4 x = src[off];
    dst[off] = make_uint2(pack_h2(x.x, x.y), pack_h2(x.z, x.w));
}

// ===========================================================================
// Shared GEMM mainloop (half inputs, cp.async 4-stage, BK=32, 128x128 tile).
// ===========================================================================
struct GemmFrag { float acc[2][8][4]; };

__device__ __forceinline__
void gemm_mainloop(const half* __restrict__ A, const half* __restrict__ W,
                   int M, int N, int K, int m0, int n0,
                   uint32_t sm_base, GemmFrag& f) {
    const int tid = threadIdx.x;
    const int warp = tid >> 5;
    const int lane = tid & 31;
    const int wm = warp & 3;
    const int wn = warp >> 2;

    auto issue_stage = [&](int kc, int s) {
        const uint32_t sa = sm_base + (uint32_t)(s * 9472) * 2;
        const uint32_t sw = sa + 5120 * 2;
#pragma unroll
        for (int t = 0; t < 2; t++) {
            int idx = tid + t * 256;
            int row = idx >> 2, c4 = idx & 3;
            cp16(sa + (uint32_t)(row * 40 + c4 * 8) * 2,
                 A + (size_t)(m0 + row) * K + kc * 32 + c4 * 8);
        }
#pragma unroll
        for (int t = 0; t < 2; t++) {
            int idx = tid + t * 256;
            int row = idx >> 4, c16 = idx & 15;
            cp16(sw + (uint32_t)(row * 136 + c16 * 8) * 2,
                 W + (size_t)(kc * 32 + row) * N + n0 + c16 * 8);
        }
        cp_commit();
    };

#pragma unroll
    for (int mi = 0; mi < 2; mi++)
#pragma unroll
        for (int nj = 0; nj < 8; nj++)
#pragma unroll
            for (int c = 0; c < 4; c++) f.acc[mi][nj][c] = 0.0f;

    issue_stage(0, 0);
    issue_stage(1, 1);

    const int nk = K / 32;
    for (int kc = 0; kc < nk; kc++) {
        const int s = kc & 3;
        if (kc + 2 < nk) { issue_stage(kc + 2, (kc + 2) & 3); cp_wait<2>(); }
        else if (kc + 1 < nk) { cp_wait<1>(); }
        else { cp_wait<0>(); }
        __syncthreads();

        const uint32_t a_base = sm_base + (uint32_t)(s * 9472) * 2;
        const uint32_t w_base = a_base + 5120 * 2;
#pragma unroll
        for (int ks = 0; ks < 2; ks++) {
            const int kb = ks * 16;
            uint32_t af[2][4];
#pragma unroll
            for (int mi = 0; mi < 2; mi++) {
                const int row = wm * 32 + mi * 16 + (lane & 15);
                const int col = kb + 8 * (lane >> 4);
                ldsm_x4(af[mi][0], af[mi][1], af[mi][2], af[mi][3],
                        a_base + (uint32_t)(row * 40 + col) * 2);
            }
#pragma unroll
            for (int nj2 = 0; nj2 < 4; nj2++) {
                const int row = kb + (lane & 7) + (((lane >> 3) & 1) * 8);
                const int col = wn * 64 + nj2 * 16 + (((lane >> 4) & 1) * 8);
                uint32_t b0r, b1r, b2r, b3r;
                ldsm_x4_t(b0r, b1r, b2r, b3r, w_base + (uint32_t)(row * 136 + col) * 2);
                uint32_t bb0[2] = {b0r, b1r}, bb1[2] = {b2r, b3r};
                mma_f16(f.acc[0][2 * nj2], af[0], bb0);
                mma_f16(f.acc[0][2 * nj2 + 1], af[0], bb1);
                mma_f16(f.acc[1][2 * nj2], af[1], bb0);
                mma_f16(f.acc[1][2 * nj2 + 1], af[1], bb1);
            }
        }
    }
}

// Fused Q/K/V projections (half out; z==0 scaled by 1/8)
__global__ __launch_bounds__(256, 2)
void gemm3_h(const half* A0, const half* A1, const half* A2,
             const half* W0, const half* W1, const half* W2,
             const float* b0, const float* b1, const float* b2,
             half* C0, half* C1, half* C2, int M, int N, int K) {
    extern __shared__ half smh[];
    const int z = blockIdx.z;
    const half* A = (z == 0) ? A0 : (z == 1) ? A1 : A2;
    const half* W = (z == 0) ? W0 : (z == 1) ? W1 : W2;
    const float* bias = (z == 0) ? b0 : (z == 1) ? b1 : b2;
    half* C = (z == 0) ? C0 : (z == 1) ? C1 : C2;
    const float scale = (z == 0) ? 0.125f : 1.0f;

    const int m0 = blockIdx.x * 128, n0 = blockIdx.y * 128;
    GemmFrag f;
    gemm_mainloop(A, W, M, N, K, m0, n0, smem_u32(smh), f);

    const int warp = threadIdx.x >> 5, lane = threadIdx.x & 31;
    const int g = lane >> 2, tg = lane & 3;
    const int wm = warp & 3, wn = warp >> 2;
#pragma unroll
    for (int mi = 0; mi < 2; mi++) {
        const int rb = m0 + wm * 32 + mi * 16;
#pragma unroll
        for (int nj = 0; nj < 8; nj++) {
            const int colb = n0 + wn * 64 + nj * 8 + 2 * tg;
            const float2 bv = *reinterpret_cast<const float2*>(bias + colb);
            *reinterpret_cast<uint32_t*>(C + (size_t)(rb + g) * N + colb) =
                pack_h2((f.acc[mi][nj][0] + bv.x) * scale, (f.acc[mi][nj][1] + bv.y) * scale);
            *reinterpret_cast<uint32_t*>(C + (size_t)(rb + g + 8) * N + colb) =
                pack_h2((f.acc[mi][nj][2] + bv.x) * scale, (f.acc[mi][nj][3] + bv.y) * scale);
        }
    }
}

// Output projection (half in, float out) — round-11 128x128 body
__global__ __launch_bounds__(256, 2)
void gemm_out_h(const half* __restrict__ A, const half* __restrict__ W,
                const float* __restrict__ bias, float* __restrict__ C,
                int M, int N, int K) {
    extern __shared__ half smh[];
    const int m0 = blockIdx.x * 128, n0 = blockIdx.y * 128;
    GemmFrag f;
    gemm_mainloop(A, W, M, N, K, m0, n0, smem_u32(smh), f);

    const int warp = threadIdx.x >> 5, lane = threadIdx.x & 31;
    const int g = lane >> 2, tg = lane & 3;
    const int wm = warp & 3, wn = warp >> 2;
#pragma unroll
    for (int mi = 0; mi < 2; mi++) {
        const int rb = m0 + wm * 32 + mi * 16;
#pragma unroll
        for (int nj = 0; nj < 8; nj++) {
            const int colb = n0 + wn * 64 + nj * 8 + 2 * tg;
            const float2 bv = *reinterpret_cast<const float2*>(bias + colb);
            *reinterpret_cast<float2*>(C + (size_t)(rb + g) * N + colb) =
                make_float2(f.acc[mi][nj][0] + bv.x, f.acc[mi][nj][1] + bv.y);
            *reinterpret_cast<float2*>(C + (size_t)(rb + g + 8) * N + colb) =
                make_float2(f.acc[mi][nj][2] + bv.x, f.acc[mi][nj][3] + bv.y);
        }
    }
}

// ===========================================================================
// Fused flash attention — fp16 mma, register-resident P, 3-stage 64-col
// cp.async K/V ring. This round: tree-reductions for row max/sum and
// double-buffered (pipelined) K/V fragment ldsm to hide LDS latency.
// smem (halfs): Q[128][72] + 3 x (K[64][72] + V[64][72]).
// ===========================================================================
__global__ __launch_bounds__(256, 2)
void attn_kernel(const half* __restrict__ Qg, const half* __restrict__ Kg,
                 const half* __restrict__ Vg, const float* __restrict__ structure,
                 half* __restrict__ ctx) {
    extern __shared__ half smh[];
    const uint32_t qs_base = smem_u32(smh);

    const int tid = threadIdx.x;
    const int warp = tid >> 5;
    const int lane = tid & 31;
    const int g = lane >> 2;
    const int tg = lane & 3;
    const int q0 = blockIdx.x * 128;
    const int h = blockIdx.y;
    const int b = blockIdx.z;
    const int rq = warp * 16;
    const size_t baseQ = ((size_t)b * SS + q0) * DD + h * 64;

    auto issue_kv = [&](int kt, int s) {
        const size_t baseK = ((size_t)b * SS + kt * 64) * DD + h * 64;
        const uint32_t kb = qs_base + (uint32_t)(9216 + s * 9216) * 2;
        const uint32_t vb = kb + 4608 * 2;
#pragma unroll
        for (int t = 0; t < 2; t++) {
            int idx = tid + t * 256;
            int row = idx >> 3, c8 = idx & 7;
            cp16(kb + (uint32_t)(row * 72 + c8 * 8) * 2,
                 Kg + baseK + (size_t)row * DD + c8 * 8);
        }
#pragma unroll
        for (int t = 0; t < 2; t++) {
            int idx = tid + t * 256;
            int row = idx >> 3, c8 = idx & 7;
            cp16(vb + (uint32_t)(row * 72 + c8 * 8) * 2,
                 Vg + baseK + (size_t)row * DD + c8 * 8);
        }
        cp_commit();
    };

    issue_kv(0, 0);
#pragma unroll
    for (int t = 0; t < 4; t++) {
        int idx = tid + t * 256;
        int row = idx >> 3, c8 = idx & 7;
        cp16(qs_base + (uint32_t)(row * 72 + c8 * 8) * 2,
             Qg + baseQ + (size_t)row * DD + c8 * 8);
    }
    cp_commit();
    cp_wait<0>();
    __syncthreads();

    // Preload Q fragments (persist in registers all kernel)
    uint32_t qf[4][4];
#pragma unroll
    for (int ks = 0; ks < 4; ks++) {
        const int row = rq + (lane & 15);
        const int col = ks * 16 + 8 * (lane >> 4);
        ldsm_x4(qf[ks][0], qf[ks][1], qf[ks][2], qf[ks][3],
                qs_base + (uint32_t)(row * 72 + col) * 2);
    }

    float m_[2] = {-1e30f, -1e30f};
    float l_[2] = {0.0f, 0.0f};   // per-lane partial sums (quad-reduced at end)
    float oacc[8][4];
#pragma unroll
    for (int nj = 0; nj < 8; nj++)
#pragma unroll
        for (int c = 0; c < 4; c++) oacc[nj][c] = 0.0f;

    // ldsm address components (fixed per lane)
    const int krow_lo = (lane & 7) + (((lane >> 4) & 1) * 8);   // QK: row within 16
    const int kcol_lo = ((lane >> 3) & 1) * 8;                  // QK: col within 16
    const int vrow_lo = (lane & 7) + (((lane >> 3) & 1) * 8);   // PV: row within 16
    const int vcol_lo = ((lane >> 4) & 1) * 8;                  // PV: col within 16

    for (int kt = 0; kt < SS / 64; kt++) {
        const int s = kt % 3;
        const int k0g = kt * 64;

        // Structure bias -> score accumulators (issued pre-barrier)
        float sacc[8][4];
#pragma unroll
        for (int nj = 0; nj < 8; nj++) {
            const int colb = k0g + nj * 8 + 2 * tg;
            const float2 s0 = *reinterpret_cast<const float2*>(
                structure + ((size_t)b * SS + q0 + rq + g) * SS + colb);
            const float2 s1 = *reinterpret_cast<const float2*>(
                structure + ((size_t)b * SS + q0 + rq + g + 8) * SS + colb);
            sacc[nj][0] = s0.x;
            sacc[nj][1] = s0.y;
            sacc[nj][2] = s1.x;
            sacc[nj][3] = s1.y;
        }

        if (kt + 1 < SS / 64) { issue_kv(kt + 1, (kt + 1) % 3); cp_wait<1>(); }
        else { cp_wait<0>(); }
        __syncthreads();

        const uint32_t ks_base = qs_base + (uint32_t)(9216 + s * 9216) * 2;
        const uint32_t vs_base = ks_base + 4608 * 2;

        // --- QK^T, pipelined K-fragment loads (double buffer) ---
        uint32_t kf[2][4];
        ldsm_x4(kf[0][0], kf[0][1], kf[0][2], kf[0][3],
                ks_base + (uint32_t)(krow_lo * 72 + kcol_lo) * 2);
#pragma unroll
        for (int idx = 0; idx < 16; idx++) {
            const int cur = idx & 1;
            if (idx + 1 < 16) {
                const int nks = (idx + 1) >> 2, nnj2 = (idx + 1) & 3;
                const int row = nnj2 * 16 + krow_lo;
                const int col = nks * 16 + kcol_lo;
                ldsm_x4(kf[cur ^ 1][0], kf[cur ^ 1][1], kf[cur ^ 1][2], kf[cur ^ 1][3],
                        ks_base + (uint32_t)(row * 72 + col) * 2);
            }
            const int ks = idx >> 2, nj2 = idx & 3;
            uint32_t bb0[2] = {kf[cur][0], kf[cur][1]};
            uint32_t bb1[2] = {kf[cur][2], kf[cur][3]};
            mma_f16(sacc[2 * nj2], qf[ks], bb0);
            mma_f16(sacc[2 * nj2 + 1], qf[ks], bb1);
        }

        // --- Online softmax: tree reductions, deferred l ---
#pragma unroll
        for (int h2 = 0; h2 < 2; h2++) {
            float mrow[8];
#pragma unroll
            for (int nj = 0; nj < 8; nj++)
                mrow[nj] = fmaxf(sacc[nj][2 * h2], sacc[nj][2 * h2 + 1]);
            float mx = fmaxf(fmaxf(fmaxf(mrow[0], mrow[1]), fmaxf(mrow[2], mrow[3])),
                             fmaxf(fmaxf(mrow[4], mrow[5]), fmaxf(mrow[6], mrow[7])));
            mx = fmaxf(mx, __shfl_xor_sync(0xffffffffu, mx, 1));
            mx = fmaxf(mx, __shfl_xor_sync(0xffffffffu, mx, 2));

            const float mn = fmaxf(m_[h2], mx);
            const float al = __expf(m_[h2] - mn);
            float rr[8];
#pragma unroll
            for (int nj = 0; nj < 8; nj++) {
                float p0 = __expf(sacc[nj][2 * h2] - mn);
                float p1 = __expf(sacc[nj][2 * h2 + 1] - mn);
                sacc[nj][2 * h2] = p0;
                sacc[nj][2 * h2 + 1] = p1;
                rr[nj] = p0 + p1;
            }
            const float rs = ((rr[0] + rr[1]) + (rr[2] + rr[3])) +
                             ((rr[4] + rr[5]) + (rr[6] + rr[7]));
            l_[h2] = l_[h2] * al + rs;
            m_[h2] = mn;
#pragma unroll
            for (int nj = 0; nj < 8; nj++) {
                oacc[nj][2 * h2] *= al;
                oacc[nj][2 * h2 + 1] *= al;
            }
        }

        // Pack all P fragments up-front (pure ALU; sacc dies here)
        uint32_t pp[4][4];
#pragma unroll
        for (int ks = 0; ks < 4; ks++) {
            pp[ks][0] = pack_h2(sacc[2 * ks][0],     sacc[2 * ks][1]);
            pp[ks][1] = pack_h2(sacc[2 * ks][2],     sacc[2 * ks][3]);
            pp[ks][2] = pack_h2(sacc[2 * ks + 1][0], sacc[2 * ks + 1][1]);
            pp[ks][3] = pack_h2(sacc[2 * ks + 1][2], sacc[2 * ks + 1][3]);
        }

        // --- PV, pipelined V-fragment loads (double buffer) ---
        uint32_t vf[2][4];
        ldsm_x4_t(vf[0][0], vf[0][1], vf[0][2], vf[0][3],
                  vs_base + (uint32_t)(vrow_lo * 72 + vcol_lo) * 2);
#pragma unroll
        for (int idx = 0; idx < 16; idx++) {
            const int cur = idx & 1;
            if (idx + 1 < 16) {
                const int nks = (idx + 1) >> 2, ndb2 = (idx + 1) & 3;
                const int row = nks * 16 + vrow_lo;
                const int col = ndb2 * 16 + vcol_lo;
                ldsm_x4_t(vf[cur ^ 1][0], vf[cur ^ 1][1], vf[cur ^ 1][2], vf[cur ^ 1][3],
                          vs_base + (uint32_t)(row * 72 + col) * 2);
            }
            const int ks = idx >> 2, db2 = idx & 3;
            uint32_t bb0[2] = {vf[cur][0], vf[cur][1]};
            uint32_t bb1[2] = {vf[cur][2], vf[cur][3]};
            mma_f16(oacc[2 * db2], pp[ks], bb0);
            mma_f16(oacc[2 * db2 + 1], pp[ks], bb1);
        }
    }

    // Final l reduction across the quad, normalize, write half ctx
#pragma unroll
    for (int h2 = 0; h2 < 2; h2++) {
        l_[h2] += __shfl_xor_sync(0xffffffffu, l_[h2], 1);
        l_[h2] += __shfl_xor_sync(0xffffffffu, l_[h2], 2);
    }
    const float inv0 = 1.0f / l_[0];
    const float inv1 = 1.0f / l_[1];
#pragma unroll
    for (int nj = 0; nj < 8; nj++) {
        const int colb = nj * 8 + 2 * tg;
        *reinterpret_cast<uint32_t*>(ctx + baseQ + (size_t)(rq + g) * DD + colb) =
            pack_h2(oacc[nj][0] * inv0, oacc[nj][1] * inv0);
        *reinterpret_cast<uint32_t*>(ctx + baseQ + (size_t)(rq + g + 8) * DD + colb) =
            pack_h2(oacc[nj][2] * inv1, oacc[nj][3] * inv1);
    }
}

// ===========================================================================
// kernel_launch
// ===========================================================================
extern "C" void kernel_launch(void* const* d_in, const int* in_sizes, int n_in,
                              void* d_out, int out_size) {
    const float* q   = (const float*)d_in[0];
    const float* k   = (const float*)d_in[1];
    const float* v   = (const float*)d_in[2];
    const float* str = (const float*)d_in[3];
    const float* Wq  = (const float*)d_in[4];
    const float* bq  = (const float*)d_in[5];
    const float* Wk  = (const float*)d_in[6];
    const float* bk  = (const float*)d_in[7];
    const float* Wv  = (const float*)d_in[8];
    const float* bv  = (const float*)d_in[9];
    const float* Wo  = (const float*)d_in[10];
    const float* bo  = (const float*)d_in[11];
    float* out = (float*)d_out;

    half *qin, *kin, *vin, *Wqh, *Wkh, *Wvh, *Woh, *Qh, *Kh, *Vh, *Ctxh;
    cudaGetSymbolAddress((void**)&qin, g_qin);
    cudaGetSymbolAddress((void**)&kin, g_kin);
    cudaGetSymbolAddress((void**)&vin, g_vin);
    cudaGetSymbolAddress((void**)&Wqh, g_Wqh);
    cudaGetSymbolAddress((void**)&Wkh, g_Wkh);
    cudaGetSymbolAddress((void**)&Wvh, g_Wvh);
    cudaGetSymbolAddress((void**)&Woh, g_Woh);
    cudaGetSymbolAddress((void**)&Qh, g_Qh);
    cudaGetSymbolAddress((void**)&Kh, g_Kh);
    cudaGetSymbolAddress((void**)&Vh, g_Vh);
    cudaGetSymbolAddress((void**)&Ctxh, g_ctxh);

    const int M = BB * SS;   // 4096
    const int N = DD;        // 512
    const int K = DD;        // 512

    // 1) convert inputs + all weights to fp16
    const int NI = BB * SS * DD / 4, NW = DD * DD / 4;
    convert_kernel<<<(3 * NI + 4 * NW) / 256, 256>>>(
        (const float4*)q, (const float4*)k, (const float4*)v,
        (const float4*)Wq, (const float4*)Wk, (const float4*)Wv, (const float4*)Wo,
        (uint2*)qin, (uint2*)kin, (uint2*)vin,
        (uint2*)Wqh, (uint2*)Wkh, (uint2*)Wvh, (uint2*)Woh);

    // 2) fused Q/K/V projections
    const int gsm = 4 * 9472 * (int)sizeof(half);   // 75776 B
    cudaFuncSetAttribute(gemm3_h, cudaFuncAttributeMaxDynamicSharedMemorySize, gsm);
    dim3 g3(M / 128, N / 128, 3);
    gemm3_h<<<g3, 256, gsm>>>(qin, kin, vin, Wqh, Wkh, Wvh,
                              bq, bk, bv, Qh, Kh, Vh, M, N, K);

    // 3) attention (half ctx out)
    const int att_smem = (9216 + 3 * 9216) * (int)sizeof(half);   // 73728 B
    cudaFuncSetAttribute(attn_kernel, cudaFuncAttributeMaxDynamicSharedMemorySize,
                         att_smem);
    dim3 att_grid(SS / 128, HH, BB);
    attn_kernel<<<att_grid, 256, att_smem>>>(Qh, Kh, Vh, str, Ctxh);

    // 4) output projection (128x128 tiles)
    cudaFuncSetAttribute(gemm_out_h, cudaFuncAttributeMaxDynamicSharedMemorySize, gsm);
    dim3 gemm_grid(M / 128, N / 128);
    gemm_out_h<<<gemm_grid, 256, gsm>>>(Ctxh, Woh, bo, out, M, N, K);
}

// round 15
// speedup vs baseline: 1.0375x; 1.0064x over previous
#include <cuda_runtime.h>
#include <cuda_fp16.h>
#include <cstdint>

#define BB 2
#define SS 2048
#define DD 512
#define HH 8

// Scratch (allocation-free: __device__ globals)
__device__ half  g_qin[BB * SS * DD];
__device__ half  g_kin[BB * SS * DD];
__device__ half  g_vin[BB * SS * DD];
__device__ half  g_Wqh[DD * DD];
__device__ half  g_Wkh[DD * DD];
__device__ half  g_Wvh[DD * DD];
__device__ half  g_Woh[DD * DD];
__device__ half  g_Qh[BB * SS * DD];
__device__ half  g_Kh[BB * SS * DD];
__device__ half  g_Vh[BB * SS * DD];
__device__ half  g_ctxh[BB * SS * DD];

// ---------------------------------------------------------------------------
// Helpers
// ---------------------------------------------------------------------------
__device__ __forceinline__ void mma_f16(float* d, const uint32_t* a, const uint32_t* b) {
    asm volatile(
        "mma.sync.aligned.m16n8k16.row.col.f32.f16.f16.f32 "
        "{%0,%1,%2,%3}, {%4,%5,%6,%7}, {%8,%9}, {%0,%1,%2,%3};"
        : "+f"(d[0]), "+f"(d[1]), "+f"(d[2]), "+f"(d[3])
        : "r"(a[0]), "r"(a[1]), "r"(a[2]), "r"(a[3]), "r"(b[0]), "r"(b[1]));
}
__device__ __forceinline__ void ldsm_x4(uint32_t& r0, uint32_t& r1, uint32_t& r2,
                                        uint32_t& r3, uint32_t addr) {
    asm volatile("ldmatrix.sync.aligned.m8n8.x4.shared.b16 {%0,%1,%2,%3}, [%4];"
                 : "=r"(r0), "=r"(r1), "=r"(r2), "=r"(r3) : "r"(addr));
}
__device__ __forceinline__ void ldsm_x4_t(uint32_t& r0, uint32_t& r1, uint32_t& r2,
                                          uint32_t& r3, uint32_t addr) {
    asm volatile("ldmatrix.sync.aligned.m8n8.x4.trans.shared.b16 {%0,%1,%2,%3}, [%4];"
                 : "=r"(r0), "=r"(r1), "=r"(r2), "=r"(r3) : "r"(addr));
}
__device__ __forceinline__ uint32_t smem_u32(const void* p) {
    uint32_t a;
    asm("{ .reg .u64 t; cvta.to.shared.u64 t, %1; cvt.u32.u64 %0, t; }"
        : "=r"(a) : "l"(p));
    return a;
}
__device__ __forceinline__ uint32_t pack_h2(float a, float b) {
    __half2 h = __floats2half2_rn(a, b);
    return *reinterpret_cast<uint32_t*>(&h);
}
__device__ __forceinline__ void cp16(uint32_t dst, const void* src) {
    asm volatile("cp.async.cg.shared.global [%0], [%1], 16;" :: "r"(dst), "l"(src));
}
__device__ __forceinline__ void cp_commit() {
    asm volatile("cp.async.commit_group;" ::: "memory");
}
template <int N>
__device__ __forceinline__ void cp_wait() {
    asm volatile("cp.async.wait_group %0;" :: "n"(N) : "memory");
}

// ===========================================================================
// Convert kernel: fp32 -> fp16 for q,k,v inputs and Wq,Wk,Wv,Wo
// ===========================================================================
__global__ __launch_bounds__(256)
void convert_kernel(const float4* q, const float4* k, const float4* v,
                    const float4* wq, const float4* wk, const float4* wv,
                    const float4* wo,
                    uint2* qh, uint2* kh, uint2* vh,
                    uint2* wqh, uint2* wkh, uint2* wvh, uint2* woh) {
    const int NI = BB * SS * DD / 4;   // 524288
    const int NW = DD * DD / 4;        // 65536
    int i = blockIdx.x * 256 + threadIdx.x;
    const float4* src; uint2* dst; int off;
    if (i < NI)                   { src = q;  dst = qh;  off = i; }
    else if (i < 2 * NI)          { src = k;  dst = kh;  off = i - NI; }
    else if (i < 3 * NI)          { src = v;  dst = vh;  off = i - 2 * NI; }
    else if (i < 3 * NI + NW)     { src = wq; dst = wqh; off = i - 3 * NI; }
    else if (i < 3 * NI + 2 * NW) { src = wk; dst = wkh; off = i - 3 * NI - NW; }
    else if (i < 3 * NI + 3 * NW) { src = wv; dst = wvh; off = i - 3 * NI - 2 * NW; }
    else                          { src = wo; dst = woh; off = i - 3 * NI - 3 * NW; }
    float4 x = src[off];
    dst[off] = make_uint2(pack_h2(x.x, x.y), pack_h2(x.z, x.w));
}

// ===========================================================================
// Shared GEMM mainloop (half inputs, cp.async 4-stage, BK=32, 128x128 tile).
// ===========================================================================
struct GemmFrag { float acc[2][8][4]; };

__device__ __forceinline__
void gemm_mainloop(const half* __restrict__ A, const half* __restrict__ W,
                   int M, int N, int K, int m0, int n0,
                   uint32_t sm_base, GemmFrag& f) {
    const int tid = threadIdx.x;
    const int warp = tid >> 5;
    const int lane = tid & 31;
    const int wm = warp & 3;
    const int wn = warp >> 2;

    auto issue_stage = [&](int kc, int s) {
        const uint32_t sa = sm_base + (uint32_t)(s * 9472) * 2;
        const uint32_t sw = sa + 5120 * 2;
#pragma unroll
        for (int t = 0; t < 2; t++) {
            int idx = tid + t * 256;
            int row = idx >> 2, c4 = idx & 3;
            cp16(sa + (uint32_t)(row * 40 + c4 * 8) * 2,
                 A + (size_t)(m0 + row) * K + kc * 32 + c4 * 8);
        }
#pragma unroll
        for (int t = 0; t < 2; t++) {
            int idx = tid + t * 256;
            int row = idx >> 4, c16 = idx & 15;
            cp16(sw + (uint32_t)(row * 136 + c16 * 8) * 2,
                 W + (size_t)(kc * 32 + row) * N + n0 + c16 * 8);
        }
        cp_commit();
    };

#pragma unroll
    for (int mi = 0; mi < 2; mi++)
#pragma unroll
        for (int nj = 0; nj < 8; nj++)
#pragma unroll
            for (int c = 0; c < 4; c++) f.acc[mi][nj][c] = 0.0f;

    issue_stage(0, 0);
    issue_stage(1, 1);

    const int nk = K / 32;
    for (int kc = 0; kc < nk; kc++) {
        const int s = kc & 3;
        if (kc + 2 < nk) { issue_stage(kc + 2, (kc + 2) & 3); cp_wait<2>(); }
        else if (kc + 1 < nk) { cp_wait<1>(); }
        else { cp_wait<0>(); }
        __syncthreads();

        const uint32_t a_base = sm_base + (uint32_t)(s * 9472) * 2;
        const uint32_t w_base = a_base + 5120 * 2;
#pragma unroll
        for (int ks = 0; ks < 2; ks++) {
            const int kb = ks * 16;
            uint32_t af[2][4];
#pragma unroll
            for (int mi = 0; mi < 2; mi++) {
                const int row = wm * 32 + mi * 16 + (lane & 15);
                const int col = kb + 8 * (lane >> 4);
                ldsm_x4(af[mi][0], af[mi][1], af[mi][2], af[mi][3],
                        a_base + (uint32_t)(row * 40 + col) * 2);
            }
#pragma unroll
            for (int nj2 = 0; nj2 < 4; nj2++) {
                const int row = kb + (lane & 7) + (((lane >> 3) & 1) * 8);
                const int col = wn * 64 + nj2 * 16 + (((lane >> 4) & 1) * 8);
                uint32_t b0r, b1r, b2r, b3r;
                ldsm_x4_t(b0r, b1r, b2r, b3r, w_base + (uint32_t)(row * 136 + col) * 2);
                uint32_t bb0[2] = {b0r, b1r}, bb1[2] = {b2r, b3r};
                mma_f16(f.acc[0][2 * nj2], af[0], bb0);
                mma_f16(f.acc[0][2 * nj2 + 1], af[0], bb1);
                mma_f16(f.acc[1][2 * nj2], af[1], bb0);
                mma_f16(f.acc[1][2 * nj2 + 1], af[1], bb1);
            }
        }
    }
}

// Fused Q/K/V projections (half out; z==0 scaled by 1/8)
__global__ __launch_bounds__(256, 2)
void gemm3_h(const half* A0, const half* A1, const half* A2,
             const half* W0, const half* W1, const half* W2,
             const float* b0, const float* b1, const float* b2,
             half* C0, half* C1, half* C2, int M, int N, int K) {
    extern __shared__ half smh[];
    const int z = blockIdx.z;
    const half* A = (z == 0) ? A0 : (z == 1) ? A1 : A2;
    const half* W = (z == 0) ? W0 : (z == 1) ? W1 : W2;
    const float* bias = (z == 0) ? b0 : (z == 1) ? b1 : b2;
    half* C = (z == 0) ? C0 : (z == 1) ? C1 : C2;
    const float scale = (z == 0) ? 0.125f : 1.0f;

    const int m0 = blockIdx.x * 128, n0 = blockIdx.y * 128;
    GemmFrag f;
    gemm_mainloop(A, W, M, N, K, m0, n0, smem_u32(smh), f);

    const int warp = threadIdx.x >> 5, lane = threadIdx.x & 31;
    const int g = lane >> 2, tg = lane & 3;
    const int wm = warp & 3, wn = warp >> 2;
#pragma unroll
    for (int mi = 0; mi < 2; mi++) {
        const int rb = m0 + wm * 32 + mi * 16;
#pragma unroll
        for (int nj = 0; nj < 8; nj++) {
            const int colb = n0 + wn * 64 + nj * 8 + 2 * tg;
            const float2 bv = *reinterpret_cast<const float2*>(bias + colb);
            *reinterpret_cast<uint32_t*>(C + (size_t)(rb + g) * N + colb) =
                pack_h2((f.acc[mi][nj][0] + bv.x) * scale, (f.acc[mi][nj][1] + bv.y) * scale);
            *reinterpret_cast<uint32_t*>(C + (size_t)(rb + g + 8) * N + colb) =
                pack_h2((f.acc[mi][nj][2] + bv.x) * scale, (f.acc[mi][nj][3] + bv.y) * scale);
        }
    }
}

// Output projection (half in, float out)
__global__ __launch_bounds__(256, 2)
void gemm_out_h(const half* __restrict__ A, const half* __restrict__ W,
                const float* __restrict__ bias, float* __restrict__ C,
                int M, int N, int K) {
    extern __shared__ half smh[];
    const int m0 = blockIdx.x * 128, n0 = blockIdx.y * 128;
    GemmFrag f;
    gemm_mainloop(A, W, M, N, K, m0, n0, smem_u32(smh), f);

    const int warp = threadIdx.x >> 5, lane = threadIdx.x & 31;
    const int g = lane >> 2, tg = lane & 3;
    const int wm = warp & 3, wn = warp >> 2;
#pragma unroll
    for (int mi = 0; mi < 2; mi++) {
        const int rb = m0 + wm * 32 + mi * 16;
#pragma unroll
        for (int nj = 0; nj < 8; nj++) {
            const int colb = n0 + wn * 64 + nj * 8 + 2 * tg;
            const float2 bv = *reinterpret_cast<const float2*>(bias + colb);
            *reinterpret_cast<float2*>(C + (size_t)(rb + g) * N + colb) =
                make_float2(f.acc[mi][nj][0] + bv.x, f.acc[mi][nj][1] + bv.y);
            *reinterpret_cast<float2*>(C + (size_t)(rb + g + 8) * N + colb) =
                make_float2(f.acc[mi][nj][2] + bv.x, f.acc[mi][nj][3] + bv.y);
        }
    }
}

// ===========================================================================
// Fused flash attention — fp16 mma, register-resident P, cross-tile PV
// pipelining. FOUR-stage 64-col cp.async K/V ring: stage (kt-1)%4 read by
// the deferred PV(kt-1) at iter kt is next rewritten by issue_kv(kt+3),
// issued at iter kt+2 — strictly after the iter-(kt+1) barrier. (The 3-stage
// ring of round 14 raced exactly here: rel_err 0.18.)
// smem (halfs): Q[128][72] + 4 x (K[64][72] + V[64][72]) = 92160 B.
// ===========================================================================
__global__ __launch_bounds__(256, 2)
void attn_kernel(const half* __restrict__ Qg, const half* __restrict__ Kg,
                 const half* __restrict__ Vg, const float* __restrict__ structure,
                 half* __restrict__ ctx) {
    extern __shared__ half smh[];
    const uint32_t qs_base = smem_u32(smh);

    const int tid = threadIdx.x;
    const int warp = tid >> 5;
    const int lane = tid & 31;
    const int g = lane >> 2;
    const int tg = lane & 3;
    const int q0 = blockIdx.x * 128;
    const int h = blockIdx.y;
    const int b = blockIdx.z;
    const int rq = warp * 16;
    const size_t baseQ = ((size_t)b * SS + q0) * DD + h * 64;

    auto issue_kv = [&](int kt, int s) {
        const size_t baseK = ((size_t)b * SS + kt * 64) * DD + h * 64;
        const uint32_t kb = qs_base + (uint32_t)(9216 + s * 9216) * 2;
        const uint32_t vb = kb + 4608 * 2;
#pragma unroll
        for (int t = 0; t < 2; t++) {
            int idx = tid + t * 256;
            int row = idx >> 3, c8 = idx & 7;
            cp16(kb + (uint32_t)(row * 72 + c8 * 8) * 2,
                 Kg + baseK + (size_t)row * DD + c8 * 8);
        }
#pragma unroll
        for (int t = 0; t < 2; t++) {
            int idx = tid + t * 256;
            int row = idx >> 3, c8 = idx & 7;
            cp16(vb + (uint32_t)(row * 72 + c8 * 8) * 2,
                 Vg + baseK + (size_t)row * DD + c8 * 8);
        }
        cp_commit();
    };

    issue_kv(0, 0);
#pragma unroll
    for (int t = 0; t < 4; t++) {
        int idx = tid + t * 256;
        int row = idx >> 3, c8 = idx & 7;
        cp16(qs_base + (uint32_t)(row * 72 + c8 * 8) * 2,
             Qg + baseQ + (size_t)row * DD + c8 * 8);
    }
    cp_commit();
    cp_wait<0>();
    __syncthreads();

    // Preload Q fragments (persist in registers)
    uint32_t qf[4][4];
#pragma unroll
    for (int ks = 0; ks < 4; ks++) {
        const int row = rq + (lane & 15);
        const int col = ks * 16 + 8 * (lane >> 4);
        ldsm_x4(qf[ks][0], qf[ks][1], qf[ks][2], qf[ks][3],
                qs_base + (uint32_t)(row * 72 + col) * 2);
    }

    float m_[2] = {-1e30f, -1e30f};
    float l_[2] = {0.0f, 0.0f};
    float oacc[8][4];
#pragma unroll
    for (int nj = 0; nj < 8; nj++)
#pragma unroll
        for (int c = 0; c < 4; c++) oacc[nj][c] = 0.0f;

    const int krow_lo = (lane & 7) + (((lane >> 4) & 1) * 8);
    const int kcol_lo = ((lane >> 3) & 1) * 8;
    const int vrow_lo = (lane & 7) + (((lane >> 3) & 1) * 8);
    const int vcol_lo = ((lane >> 4) & 1) * 8;

    // PV for one tile: pp (A-frags) x V-from-smem (trans ldsm, double-buffered)
    auto pv_tile = [&](uint32_t vs_base, const uint32_t pp[4][4]) {
        uint32_t vf[2][4];
        ldsm_x4_t(vf[0][0], vf[0][1], vf[0][2], vf[0][3],
                  vs_base + (uint32_t)(vrow_lo * 72 + vcol_lo) * 2);
#pragma unroll
        for (int idx = 0; idx < 16; idx++) {
            const int cur = idx & 1;
            if (idx + 1 < 16) {
                const int nks = (idx + 1) >> 2, ndb2 = (idx + 1) & 3;
                const int row = nks * 16 + vrow_lo;
                const int col = ndb2 * 16 + vcol_lo;
                ldsm_x4_t(vf[cur ^ 1][0], vf[cur ^ 1][1], vf[cur ^ 1][2], vf[cur ^ 1][3],
                          vs_base + (uint32_t)(row * 72 + col) * 2);
            }
            const int ks = idx >> 2, db2 = idx & 3;
            uint32_t bb0[2] = {vf[cur][0], vf[cur][1]};
            uint32_t bb1[2] = {vf[cur][2], vf[cur][3]};
            mma_f16(oacc[2 * db2], pp[ks], bb0);
            mma_f16(oacc[2 * db2 + 1], pp[ks], bb1);
        }
    };

    uint32_t pp_prev[4][4];      // P fragments of tile kt-1
    uint32_t prev_vs = 0;        // V smem base of tile kt-1

    const int NT = SS / 64;      // 32
    for (int kt = 0; kt < NT; kt++) {
        const int s = kt & 3;    // 4-stage ring
        const int k0g = kt * 64;

        // Structure bias -> score accumulators (issued pre-barrier)
        float sacc[8][4];
#pragma unroll
        for (int nj = 0; nj < 8; nj++) {
            const int colb = k0g + nj * 8 + 2 * tg;
            const float2 s0 = *reinterpret_cast<const float2*>(
                structure + ((size_t)b * SS + q0 + rq + g) * SS + colb);
            const float2 s1 = *reinterpret_cast<const float2*>(
                structure + ((size_t)b * SS + q0 + rq + g + 8) * SS + colb);
            sacc[nj][0] = s0.x;
            sacc[nj][1] = s0.y;
            sacc[nj][2] = s1.x;
            sacc[nj][3] = s1.y;
        }

        if (kt + 1 < NT) { issue_kv(kt + 1, (kt + 1) & 3); cp_wait<1>(); }
        else { cp_wait<0>(); }
        __syncthreads();

        const uint32_t ks_base = qs_base + (uint32_t)(9216 + s * 9216) * 2;
        const uint32_t vs_base = ks_base + 4608 * 2;

        // --- QK^T (double-buffered K frags) ---
        uint32_t kf[2][4];
        ldsm_x4(kf[0][0], kf[0][1], kf[0][2], kf[0][3],
                ks_base + (uint32_t)(krow_lo * 72 + kcol_lo) * 2);
#pragma unroll
        for (int idx = 0; idx < 16; idx++) {
            const int cur = idx & 1;
            if (idx + 1 < 16) {
                const int nks = (idx + 1) >> 2, nnj2 = (idx + 1) & 3;
                const int row = nnj2 * 16 + krow_lo;
                const int col = nks * 16 + kcol_lo;
                ldsm_x4(kf[cur ^ 1][0], kf[cur ^ 1][1], kf[cur ^ 1][2], kf[cur ^ 1][3],
                        ks_base + (uint32_t)(row * 72 + col) * 2);
            }
            const int ks = idx >> 2, nj2 = idx & 3;
            uint32_t bb0[2] = {kf[cur][0], kf[cur][1]};
            uint32_t bb1[2] = {kf[cur][2], kf[cur][3]};
            mma_f16(sacc[2 * nj2], qf[ks], bb0);
            mma_f16(sacc[2 * nj2 + 1], qf[ks], bb1);
        }

        // --- Softmax part 1 (mx/al/exp/l; does NOT touch oacc) ---
        float al2[2];
#pragma unroll
        for (int h2 = 0; h2 < 2; h2++) {
            float mrow[8];
#pragma unroll
            for (int nj = 0; nj < 8; nj++)
                mrow[nj] = fmaxf(sacc[nj][2 * h2], sacc[nj][2 * h2 + 1]);
            float mx = fmaxf(fmaxf(fmaxf(mrow[0], mrow[1]), fmaxf(mrow[2], mrow[3])),
                             fmaxf(fmaxf(mrow[4], mrow[5]), fmaxf(mrow[6], mrow[7])));
            mx = fmaxf(mx, __shfl_xor_sync(0xffffffffu, mx, 1));
            mx = fmaxf(mx, __shfl_xor_sync(0xffffffffu, mx, 2));

            const float mn = fmaxf(m_[h2], mx);
            al2[h2] = __expf(m_[h2] - mn);
            float rr[8];
#pragma unroll
            for (int nj = 0; nj < 8; nj++) {
                float p0 = __expf(sacc[nj][2 * h2] - mn);
                float p1 = __expf(sacc[nj][2 * h2 + 1] - mn);
                sacc[nj][2 * h2] = p0;
                sacc[nj][2 * h2 + 1] = p1;
                rr[nj] = p0 + p1;
            }
            const float rs = ((rr[0] + rr[1]) + (rr[2] + rr[3])) +
                             ((rr[4] + rr[5]) + (rr[6] + rr[7]));
            l_[h2] = l_[h2] * al2[h2] + rs;
            m_[h2] = mn;
        }

        // --- PV of PREVIOUS tile (independent of softmax above: overlaps it) ---
        if (kt > 0) pv_tile(prev_vs, pp_prev);

        // --- oacc rescale by al(t), then capture this tile's P fragments ---
#pragma unroll
        for (int h2 = 0; h2 < 2; h2++)
#pragma unroll
            for (int nj = 0; nj < 8; nj++) {
                oacc[nj][2 * h2] *= al2[h2];
                oacc[nj][2 * h2 + 1] *= al2[h2];
            }
#pragma unroll
        for (int ks = 0; ks < 4; ks++) {
            pp_prev[ks][0] = pack_h2(sacc[2 * ks][0],     sacc[2 * ks][1]);
            pp_prev[ks][1] = pack_h2(sacc[2 * ks][2],     sacc[2 * ks][3]);
            pp_prev[ks][2] = pack_h2(sacc[2 * ks + 1][0], sacc[2 * ks + 1][1]);
            pp_prev[ks][3] = pack_h2(sacc[2 * ks + 1][2], sacc[2 * ks + 1][3]);
        }
        prev_vs = vs_base;
    }

    // Drain: PV of the last tile
    pv_tile(prev_vs, pp_prev);

    // Final l reduction across the quad, normalize, write half ctx
#pragma unroll
    for (int h2 = 0; h2 < 2; h2++) {
        l_[h2] += __shfl_xor_sync(0xffffffffu, l_[h2], 1);
        l_[h2] += __shfl_xor_sync(0xffffffffu, l_[h2], 2);
    }
    const float inv0 = 1.0f / l_[0];
    const float inv1 = 1.0f / l_[1];
#pragma unroll
    for (int nj = 0; nj < 8; nj++) {
        const int colb = nj * 8 + 2 * tg;
        *reinterpret_cast<uint32_t*>(ctx + baseQ + (size_t)(rq + g) * DD + colb) =
            pack_h2(oacc[nj][0] * inv0, oacc[nj][1] * inv0);
        *reinterpret_cast<uint32_t*>(ctx + baseQ + (size_t)(rq + g + 8) * DD + colb) =
            pack_h2(oacc[nj][2] * inv1, oacc[nj][3] * inv1);
    }
}

// ===========================================================================
// kernel_launch
// ===========================================================================
extern "C" void kernel_launch(void* const* d_in, const int* in_sizes, int n_in,
                              void* d_out, int out_size) {
    const float* q   = (const float*)d_in[0];
    const float* k   = (const float*)d_in[1];
    const float* v   = (const float*)d_in[2];
    const float* str = (const float*)d_in[3];
    const float* Wq  = (const float*)d_in[4];
    const float* bq  = (const float*)d_in[5];
    const float* Wk  = (const float*)d_in[6];
    const float* bk  = (const float*)d_in[7];
    const float* Wv  = (const float*)d_in[8];
    const float* bv  = (const float*)d_in[9];
    const float* Wo  = (const float*)d_in[10];
    const float* bo  = (const float*)d_in[11];
    float* out = (float*)d_out;

    half *qin, *kin, *vin, *Wqh, *Wkh, *Wvh, *Woh, *Qh, *Kh, *Vh, *Ctxh;
    cudaGetSymbolAddress((void**)&qin, g_qin);
    cudaGetSymbolAddress((void**)&kin, g_kin);
    cudaGetSymbolAddress((void**)&vin, g_vin);
    cudaGetSymbolAddress((void**)&Wqh, g_Wqh);
    cudaGetSymbolAddress((void**)&Wkh, g_Wkh);
    cudaGetSymbolAddress((void**)&Wvh, g_Wvh);
    cudaGetSymbolAddress((void**)&Woh, g_Woh);
    cudaGetSymbolAddress((void**)&Qh, g_Qh);
    cudaGetSymbolAddress((void**)&Kh, g_Kh);
    cudaGetSymbolAddress((void**)&Vh, g_Vh);
    cudaGetSymbolAddress((void**)&Ctxh, g_ctxh);

    const int M = BB * SS;   // 4096
    const int N = DD;        // 512
    const int K = DD;        // 512

    // 1) convert inputs + all weights to fp16
    const int NI = BB * SS * DD / 4, NW = DD * DD / 4;
    convert_kernel<<<(3 * NI + 4 * NW) / 256, 256>>>(
        (const float4*)q, (const float4*)k, (const float4*)v,
        (const float4*)Wq, (const float4*)Wk, (const float4*)Wv, (const float4*)Wo,
        (uint2*)qin, (uint2*)kin, (uint2*)vin,
        (uint2*)Wqh, (uint2*)Wkh, (uint2*)Wvh, (uint2*)Woh);

    // 2) fused Q/K/V projections
    const int gsm = 4 * 9472 * (int)sizeof(half);   // 75776 B
    cudaFuncSetAttribute(gemm3_h, cudaFuncAttributeMaxDynamicSharedMemorySize, gsm);
    dim3 g3(M / 128, N / 128, 3);
    gemm3_h<<<g3, 256, gsm>>>(qin, kin, vin, Wqh, Wkh, Wvh,
                              bq, bk, bv, Qh, Kh, Vh, M, N, K);

    // 3) attention (half ctx out), 4-stage ring
    const int att_smem = (9216 + 4 * 9216) * (int)sizeof(half);   // 92160 B
    cudaFuncSetAttribute(attn_kernel, cudaFuncAttributeMaxDynamicSharedMemorySize,
                         att_smem);
    dim3 att_grid(SS / 128, HH, BB);
    attn_kernel<<<att_grid, 256, att_smem>>>(Qh, Kh, Vh, str, Ctxh);

    // 4) output projection (128x128 tiles)
    cudaFuncSetAttribute(gemm_out_h, cudaFuncAttributeMaxDynamicSharedMemorySize, gsm);
    dim3 gemm_grid(M / 128, N / 128);
    gemm_out_h<<<gemm_grid, 256, gsm>>>(Ctxh, Woh, bo, out, M, N, K);
}